// round 3
// baseline (speedup 1.0000x reference)
#include <cuda_runtime.h>
#include <cstdint>

#define NN      100000
#define EE      1600000
#define CC      25000
#define PF      4
#define BM_WORDS 9765625u
#define WPB      2048
#define NBLK     4769          // ceil(BM_WORDS / WPB)
#define SHB      98            // hist-scan blocks

#define XNEW_OFF  0
#define POS_OFF   3200000
#define IDX_OFF   3275000
#define ATTR_OFF  6475000
#define BATCH_OFF 11275000

#define VALM 0x3FFFFFFFu
#define AGGF 0x40000000u
#define PREF 0x80000000u

static __device__ unsigned long long g_bitmap[BM_WORDS];
static __device__ float    g_cagg_x[CC * 128];
static __device__ float    g_cagg_e[CC * 4];
static __device__ float    g_newpos[CC * 3];
static __device__ float    g_W1[128 * 128];
static __device__ float    g_W2[3 * 128];
static __device__ unsigned g_hist[CC];
static __device__ unsigned g_start[CC];
static __device__ unsigned g_cursor[CC];
static __device__ int      g_binned_src[EE];
static __device__ unsigned g_ubState[NBLK];   // uniq lookback states
static __device__ unsigned g_shState[SHB];    // hist-scan lookback states

// ---------------------------------------------------------------------------
__device__ __forceinline__ unsigned lookback(unsigned* state, int b, unsigned agg) {
    if (b == 0) {
        __threadfence();
        atomicExch(&state[0], PREF | agg);
        return 0u;
    }
    atomicExch(&state[b], AGGF | agg);
    unsigned prefix = 0;
    int i = b - 1;
    while (true) {
        unsigned s;
        do { s = atomicAdd(&state[i], 0u); } while (!(s & (AGGF | PREF)));
        prefix += s & VALM;
        if (s & PREF) break;
        i--;
    }
    __threadfence();
    atomicExch(&state[b], PREF | (agg + prefix));
    return prefix;
}

__device__ __forceinline__ unsigned block_excl_scan256(unsigned v, unsigned* s_warp,
                                                       unsigned* total) {
    unsigned lane = threadIdx.x & 31, wid = threadIdx.x >> 5;
    unsigned x = v;
    #pragma unroll
    for (int o = 1; o < 32; o <<= 1) {
        unsigned y = __shfl_up_sync(0xffffffffu, x, o);
        if (lane >= o) x += y;
    }
    if (lane == 31) s_warp[wid] = x;
    __syncthreads();
    if (wid == 0) {
        unsigned t = (lane < 8) ? s_warp[lane] : 0u;
        #pragma unroll
        for (int o = 1; o < 8; o <<= 1) {
            unsigned y = __shfl_up_sync(0xffffffffu, t, o);
            if (lane >= o) t += y;
        }
        if (lane < 8) s_warp[lane] = t;
    }
    __syncthreads();
    unsigned warpBase = wid ? s_warp[wid - 1] : 0u;
    unsigned excl = warpBase + x - v;
    *total = s_warp[7];
    __syncthreads();
    return excl;
}

// ---------------------------------------------------------------------------
// K_init: blocks [0,98): new_pos/new_batch ; [98,229): weight GEMMs ;
//         [229,269): zero scratch/state arrays
__global__ void k_init(const float* __restrict__ pos,
                       const int* __restrict__ batch,
                       const float* __restrict__ Wc,
                       const float* __restrict__ We,
                       const float* __restrict__ Wg,
                       float* __restrict__ out) {
    if (blockIdx.x < 98) {
        int c = blockIdx.x * 256 + threadIdx.x;
        if (c >= CC) return;
        float s0 = 0.f, s1 = 0.f, s2 = 0.f;
        int bmax = -2147483647;
        #pragma unroll
        for (int i = 0; i < PF; i++) {
            int n = c * PF + i;
            s0 += pos[n * 3 + 0];
            s1 += pos[n * 3 + 1];
            s2 += pos[n * 3 + 2];
            int b = batch[n];
            bmax = b > bmax ? b : bmax;
        }
        s0 *= 0.25f; s1 *= 0.25f; s2 *= 0.25f;
        g_newpos[c * 3 + 0] = s0;
        g_newpos[c * 3 + 1] = s1;
        g_newpos[c * 3 + 2] = s2;
        out[POS_OFF + c * 3 + 0] = s0;
        out[POS_OFF + c * 3 + 1] = s1;
        out[POS_OFF + c * 3 + 2] = s2;
        out[BATCH_OFF + c] = (float)bmax;
    } else if (blockIdx.x < 229) {
        int i = blockIdx.x - 98;       // 0..130
        int j = threadIdx.x;
        if (j >= 128) return;
        if (i < 128) {
            float s = 0.f;
            #pragma unroll 8
            for (int k = 0; k < 128; k++) s += Wc[i * 144 + 16 + k] * Wg[k * 128 + j];
            g_W1[i * 128 + j] = s;
        } else {
            int r = i - 128;
            float s = 0.f;
            #pragma unroll 8
            for (int k = 0; k < 128; k++) s += We[r * 144 + 16 + k] * Wg[k * 128 + j];
            g_W2[r * 128 + j] = s;
        }
    } else {
        int t = (blockIdx.x - 229) * 256 + threadIdx.x;
        const int S = 40 * 256;
        for (int i = t; i < CC * 4; i += S) g_cagg_e[i] = 0.f;
        for (int i = t; i < CC; i += S) g_hist[i] = 0u;
        for (int i = t; i < NBLK; i += S) g_ubState[i] = 0u;
        for (int i = t; i < SHB; i += S) g_shState[i] = 0u;
    }
}

// ---------------------------------------------------------------------------
// K_hist: cluster histogram + bitmap set + edge_attr atomics
__global__ __launch_bounds__(256) void k_hist(const int* __restrict__ ei,
                                              const float* __restrict__ ea) {
    int e = blockIdx.x * 256 + threadIdx.x;
    if (e >= EE) return;
    int src = ei[e];
    int dst = ei[EE + e];
    int c = dst >> 2;
    unsigned enc = (unsigned)(src >> 2) * (unsigned)CC + (unsigned)c;
    atomicOr(&g_bitmap[enc >> 6], 1ull << (enc & 63));
    atomicAdd(&g_hist[c], 1u);
    float a0 = ea[3 * e + 0], a1 = ea[3 * e + 1], a2 = ea[3 * e + 2];
    atomicAdd(&g_cagg_e[c * 4 + 0], a0);
    atomicAdd(&g_cagg_e[c * 4 + 1], a1);
    atomicAdd(&g_cagg_e[c * 4 + 2], a2);
}

// ---------------------------------------------------------------------------
// K_scanH: exclusive scan of 25000 cluster counts, decoupled lookback
__global__ __launch_bounds__(256) void k_scanH() {
    __shared__ unsigned s_warp[8];
    __shared__ unsigned sh_base;
    int b = blockIdx.x, tid = threadIdx.x;
    int idx = b * 256 + tid;
    unsigned v = (idx < CC) ? g_hist[idx] : 0u;
    unsigned total;
    unsigned excl = block_excl_scan256(v, s_warp, &total);
    if (tid == 0) sh_base = lookback(g_shState, b, total);
    __syncthreads();
    if (idx < CC) {
        unsigned st = sh_base + excl;
        g_start[idx] = st;
        g_cursor[idx] = st;
    }
}

// ---------------------------------------------------------------------------
// K_fill: place src node into its dst-cluster bin
__global__ __launch_bounds__(256) void k_fill(const int* __restrict__ ei) {
    int e = blockIdx.x * 256 + threadIdx.x;
    if (e >= EE) return;
    int src = ei[e];
    int dst = ei[EE + e];
    int c = dst >> 2;
    unsigned p = atomicAdd(&g_cursor[c], 1u);
    g_binned_src[p] = src;
}

// ---------------------------------------------------------------------------
// K_cluster: one warp per cluster; register accumulation, write row once
__global__ __launch_bounds__(256) void k_cluster(const float* __restrict__ x) {
    int warp = (blockIdx.x * 256 + threadIdx.x) >> 5;
    int lane = threadIdx.x & 31;
    if (warp >= CC) return;
    unsigned base = g_start[warp];
    unsigned cnt = g_hist[warp];
    const float4* x4 = (const float4*)x;
    float4 acc = make_float4(0.f, 0.f, 0.f, 0.f);

    unsigned k = 0;
    for (; k + 32 <= cnt; k += 32) {
        int s = g_binned_src[base + k + lane];
        #pragma unroll
        for (int j = 0; j < 32; j++) {
            int sb = __shfl_sync(0xffffffffu, s, j);
            float4 v = __ldg(&x4[(size_t)sb * 32 + lane]);
            acc.x += v.x; acc.y += v.y; acc.z += v.z; acc.w += v.w;
        }
    }
    int rem = (int)(cnt - k);
    if (rem > 0) {
        int s = (lane < rem) ? g_binned_src[base + k + lane] : 0;
        for (int j = 0; j < rem; j++) {
            int sb = __shfl_sync(0xffffffffu, s, j);
            float4 v = __ldg(&x4[(size_t)sb * 32 + lane]);
            acc.x += v.x; acc.y += v.y; acc.z += v.z; acc.w += v.w;
        }
    }
    ((float4*)g_cagg_x)[(size_t)warp * 32 + lane] = acc;
}

// ---------------------------------------------------------------------------
// K_uniq: fused count + global scan (decoupled lookback) + sorted emit.
// Each thread owns 8 CONSECUTIVE bitmap words -> block-contiguous ordering.
// Clears every nonzero bitmap word after use (self-clean for next replay).
__global__ __launch_bounds__(256) void k_uniq(float* __restrict__ out) {
    __shared__ unsigned s_warp[8];
    __shared__ unsigned sh_base;
    int b = blockIdx.x, tid = threadIdx.x;
    size_t wbase = (size_t)b * WPB + (size_t)tid * 8;

    unsigned long long w[8];
    unsigned cnt = 0;
    #pragma unroll
    for (int j = 0; j < 8; j++) {
        size_t wi = wbase + j;
        w[j] = (wi < BM_WORDS) ? g_bitmap[wi] : 0ull;
        cnt += (unsigned)__popcll(w[j]);
    }
    unsigned total;
    unsigned excl = block_excl_scan256(cnt, s_warp, &total);
    if (tid == 0) sh_base = lookback(g_ubState, b, total);
    __syncthreads();
    unsigned p = sh_base + excl;

    #pragma unroll
    for (int j = 0; j < 8; j++) {
        unsigned long long wv = w[j];
        if (!wv) continue;
        size_t wi = wbase + j;
        g_bitmap[wi] = 0ull;                    // self-clean
        while (wv) {
            int bit = __ffsll((long long)wv) - 1;
            wv &= wv - 1;
            unsigned v = (unsigned)wi * 64u + (unsigned)bit;
            unsigned sc = v / (unsigned)CC;
            unsigned dc = v - sc * (unsigned)CC;
            out[IDX_OFF + p]      = (float)sc;
            out[IDX_OFF + EE + p] = (float)dc;
            out[ATTR_OFF + 3 * p + 0] = g_newpos[dc * 3 + 0] - g_newpos[sc * 3 + 0];
            out[ATTR_OFF + 3 * p + 1] = g_newpos[dc * 3 + 1] - g_newpos[sc * 3 + 1];
            out[ATTR_OFF + 3 * p + 2] = g_newpos[dc * 3 + 2] - g_newpos[sc * 3 + 2];
            p++;
        }
    }
}

// ---------------------------------------------------------------------------
// K_final: blocks [0,1563): x_new GEMM ; [1563,1819): zero tail of idx/attr
__global__ __launch_bounds__(256) void k_final(float* __restrict__ out) {
    if (blockIdx.x < 1563) {
        __shared__ float s_rows[16][128];
        int col = threadIdx.x & 127;
        int ty = threadIdx.x >> 7;
        int r0 = blockIdx.x * 16;
        for (int i = threadIdx.x; i < 16 * 128; i += 256) {
            int rr = i >> 7, cc = i & 127;
            int gr = r0 + rr;
            s_rows[rr][cc] = (gr < CC) ? g_cagg_x[(size_t)gr * 128 + cc] : 0.f;
        }
        __syncthreads();
        float acc[8] = {0.f, 0.f, 0.f, 0.f, 0.f, 0.f, 0.f, 0.f};
        #pragma unroll 8
        for (int k = 0; k < 128; k += 4) {
            float w0 = __ldg(&g_W1[(k + 0) * 128 + col]);
            float w1 = __ldg(&g_W1[(k + 1) * 128 + col]);
            float w2 = __ldg(&g_W1[(k + 2) * 128 + col]);
            float w3 = __ldg(&g_W1[(k + 3) * 128 + col]);
            #pragma unroll
            for (int r = 0; r < 8; r++) {
                float4 cv = *(const float4*)&s_rows[ty * 8 + r][k];
                acc[r] += cv.x * w0 + cv.y * w1 + cv.z * w2 + cv.w * w3;
            }
        }
        float e0 = __ldg(&g_W2[0 * 128 + col]);
        float e1 = __ldg(&g_W2[1 * 128 + col]);
        float e2 = __ldg(&g_W2[2 * 128 + col]);
        #pragma unroll
        for (int r = 0; r < 8; r++) {
            int gr = r0 + ty * 8 + r;
            if (gr < CC) {
                float ce0 = g_cagg_e[gr * 4 + 0];
                float ce1 = g_cagg_e[gr * 4 + 1];
                float ce2 = g_cagg_e[gr * 4 + 2];
                float res = (acc[r] + ce0 * e0 + ce1 * e1 + ce2 * e2) * 0.25f;
                out[XNEW_OFF + (size_t)gr * 128 + col] = res;
            }
        }
    } else {
        unsigned U = g_ubState[NBLK - 1] & VALM;   // total unique count
        int t = (blockIdx.x - 1563) * 256 + threadIdx.x;
        const int S = 256 * 256;
        for (int p = t; p < EE; p += S) {
            if ((unsigned)p >= U) {
                out[IDX_OFF + p] = 0.f;
                out[IDX_OFF + EE + p] = 0.f;
                out[ATTR_OFF + 3 * p + 0] = 0.f;
                out[ATTR_OFF + 3 * p + 1] = 0.f;
                out[ATTR_OFF + 3 * p + 2] = 0.f;
            }
        }
    }
}

// ---------------------------------------------------------------------------
extern "C" void kernel_launch(void* const* d_in, const int* in_sizes, int n_in,
                              void* d_out, int out_size) {
    const float* x   = (const float*)d_in[0];
    const float* pos = (const float*)d_in[1];
    const int*   ei  = (const int*)d_in[2];
    const float* ea  = (const float*)d_in[3];
    const int*   bat = (const int*)d_in[4];
    const float* Wc  = (const float*)d_in[5];
    const float* We  = (const float*)d_in[6];
    const float* Wg  = (const float*)d_in[8];
    float* out = (float*)d_out;

    k_init<<<269, 256>>>(pos, bat, Wc, We, Wg, out);
    k_hist<<<EE / 256, 256>>>(ei, ea);
    k_scanH<<<SHB, 256>>>();
    k_fill<<<EE / 256, 256>>>(ei);
    k_cluster<<<(CC * 32 + 255) / 256, 256>>>(x);
    k_uniq<<<NBLK, 256>>>(out);
    k_final<<<1819, 256>>>(out);
}

// round 5
// speedup vs baseline: 1.0780x; 1.0780x over previous
#include <cuda_runtime.h>
#include <cstdint>

#define NN      100000
#define EE      1600000
#define CC      25000
#define PF      4
#define BM_WORDS 9765625u
#define WPB      2048
#define NBLK     4769          // ceil(BM_WORDS / WPB)
#define SHB      98            // hist-scan blocks

#define XNEW_OFF  0
#define POS_OFF   3200000
#define IDX_OFF   3275000
#define ATTR_OFF  6475000
#define BATCH_OFF 11275000

#define VALM 0x3FFFFFFFu
#define AGGF 0x40000000u
#define PREF 0x80000000u

static __device__ unsigned long long g_bitmap[BM_WORDS];
static __device__ float    g_cagg_x[CC * 128];
static __device__ float    g_cagg_e[CC * 4];
static __device__ float    g_newpos[CC * 3];
static __device__ float    g_W1[128 * 128];
static __device__ float    g_W2[3 * 128];
static __device__ unsigned g_hist[CC];
static __device__ unsigned g_start[CC];
static __device__ unsigned g_cursor[CC];
static __device__ int      g_binned_src[EE];
static __device__ unsigned g_ubState[NBLK];
static __device__ unsigned g_shState[SHB];

// ---------------------------------------------------------------------------
__device__ __forceinline__ unsigned lookback(unsigned* state, int b, unsigned agg) {
    if (b == 0) {
        __threadfence();
        atomicExch(&state[0], PREF | agg);
        return 0u;
    }
    atomicExch(&state[b], AGGF | agg);
    unsigned prefix = 0;
    int i = b - 1;
    while (true) {
        unsigned s;
        do { s = atomicAdd(&state[i], 0u); } while (!(s & (AGGF | PREF)));
        prefix += s & VALM;
        if (s & PREF) break;
        i--;
    }
    __threadfence();
    atomicExch(&state[b], PREF | (agg + prefix));
    return prefix;
}

__device__ __forceinline__ unsigned block_excl_scan256(unsigned v, unsigned* s_warp,
                                                       unsigned* total) {
    unsigned lane = threadIdx.x & 31, wid = threadIdx.x >> 5;
    unsigned x = v;
    #pragma unroll
    for (int o = 1; o < 32; o <<= 1) {
        unsigned y = __shfl_up_sync(0xffffffffu, x, o);
        if (lane >= o) x += y;
    }
    if (lane == 31) s_warp[wid] = x;
    __syncthreads();
    if (wid == 0) {
        unsigned t = (lane < 8) ? s_warp[lane] : 0u;
        #pragma unroll
        for (int o = 1; o < 8; o <<= 1) {
            unsigned y = __shfl_up_sync(0xffffffffu, t, o);
            if (lane >= o) t += y;
        }
        if (lane < 8) s_warp[lane] = t;
    }
    __syncthreads();
    unsigned warpBase = wid ? s_warp[wid - 1] : 0u;
    unsigned excl = warpBase + x - v;
    *total = s_warp[7];
    __syncthreads();
    return excl;
}

// ---------------------------------------------------------------------------
// K_init: [0,98): new_pos/new_batch ; [98,229): weight GEMMs ; [229,269): zeros
__global__ void k_init(const float* __restrict__ pos,
                       const int* __restrict__ batch,
                       const float* __restrict__ Wc,
                       const float* __restrict__ We,
                       const float* __restrict__ Wg,
                       float* __restrict__ out) {
    if (blockIdx.x < 98) {
        int c = blockIdx.x * 256 + threadIdx.x;
        if (c >= CC) return;
        float s0 = 0.f, s1 = 0.f, s2 = 0.f;
        int bmax = -2147483647;
        #pragma unroll
        for (int i = 0; i < PF; i++) {
            int n = c * PF + i;
            s0 += pos[n * 3 + 0];
            s1 += pos[n * 3 + 1];
            s2 += pos[n * 3 + 2];
            int b = batch[n];
            bmax = b > bmax ? b : bmax;
        }
        s0 *= 0.25f; s1 *= 0.25f; s2 *= 0.25f;
        g_newpos[c * 3 + 0] = s0;
        g_newpos[c * 3 + 1] = s1;
        g_newpos[c * 3 + 2] = s2;
        out[POS_OFF + c * 3 + 0] = s0;
        out[POS_OFF + c * 3 + 1] = s1;
        out[POS_OFF + c * 3 + 2] = s2;
        out[BATCH_OFF + c] = (float)bmax;
    } else if (blockIdx.x < 229) {
        int i = blockIdx.x - 98;
        int j = threadIdx.x;
        if (j >= 128) return;
        if (i < 128) {
            float s = 0.f;
            #pragma unroll 8
            for (int k = 0; k < 128; k++) s += Wc[i * 144 + 16 + k] * Wg[k * 128 + j];
            g_W1[i * 128 + j] = s;
        } else {
            int r = i - 128;
            float s = 0.f;
            #pragma unroll 8
            for (int k = 0; k < 128; k++) s += We[r * 144 + 16 + k] * Wg[k * 128 + j];
            g_W2[r * 128 + j] = s;
        }
    } else {
        int t = (blockIdx.x - 229) * 256 + threadIdx.x;
        const int S = 40 * 256;
        for (int i = t; i < CC * 4; i += S) g_cagg_e[i] = 0.f;
        for (int i = t; i < CC; i += S) g_hist[i] = 0u;
        for (int i = t; i < NBLK; i += S) g_ubState[i] = 0u;
        for (int i = t; i < SHB; i += S) g_shState[i] = 0u;
    }
}

// ---------------------------------------------------------------------------
// K_bitmap: per-edge bitmap set (4 edges/thread for MLP)
__global__ __launch_bounds__(256) void k_bitmap(const int* __restrict__ ei) {
    int base = blockIdx.x * 1024 + threadIdx.x;
    int e[4]; unsigned enc[4];
    #pragma unroll
    for (int i = 0; i < 4; i++) e[i] = base + i * 256;
    int sv[4], dv[4];
    #pragma unroll
    for (int i = 0; i < 4; i++) {
        bool ok = e[i] < EE;
        sv[i] = ok ? ei[e[i]] : 0;
        dv[i] = ok ? ei[EE + e[i]] : 0;
    }
    #pragma unroll
    for (int i = 0; i < 4; i++)
        enc[i] = (unsigned)(sv[i] >> 2) * (unsigned)CC + (unsigned)(dv[i] >> 2);
    #pragma unroll
    for (int i = 0; i < 4; i++)
        if (e[i] < EE) atomicOr(&g_bitmap[enc[i] >> 6], 1ull << (enc[i] & 63));
}

// ---------------------------------------------------------------------------
// K_hist: cluster histogram + edge_attr atomics (4 edges/thread)
__global__ __launch_bounds__(256) void k_hist(const int* __restrict__ ei,
                                              const float* __restrict__ ea) {
    int base = blockIdx.x * 1024 + threadIdx.x;
    #pragma unroll
    for (int i = 0; i < 4; i++) {
        int e = base + i * 256;
        if (e >= EE) continue;
        int c = ei[EE + e] >> 2;
        atomicAdd(&g_hist[c], 1u);
        float a0 = ea[3 * e + 0], a1 = ea[3 * e + 1], a2 = ea[3 * e + 2];
        atomicAdd(&g_cagg_e[c * 4 + 0], a0);
        atomicAdd(&g_cagg_e[c * 4 + 1], a1);
        atomicAdd(&g_cagg_e[c * 4 + 2], a2);
    }
}

// ---------------------------------------------------------------------------
// K_scanH: exclusive scan of cluster counts (decoupled lookback)
__global__ __launch_bounds__(256) void k_scanH() {
    __shared__ unsigned s_warp[8];
    __shared__ unsigned sh_base;
    int b = blockIdx.x, tid = threadIdx.x;
    int idx = b * 256 + tid;
    unsigned v = (idx < CC) ? g_hist[idx] : 0u;
    unsigned total;
    unsigned excl = block_excl_scan256(v, s_warp, &total);
    if (tid == 0) sh_base = lookback(g_shState, b, total);
    __syncthreads();
    if (idx < CC) {
        unsigned st = sh_base + excl;
        g_start[idx] = st;
        g_cursor[idx] = st;
    }
}

// ---------------------------------------------------------------------------
// K_fill: place srcs into dst-cluster bins (4 edges/thread for MLP)
__global__ __launch_bounds__(256) void k_fill(const int* __restrict__ ei) {
    int base = blockIdx.x * 1024 + threadIdx.x;
    int sv[4]; unsigned p[4]; bool ok[4];
    #pragma unroll
    for (int i = 0; i < 4; i++) {
        int e = base + i * 256;
        ok[i] = e < EE;
        sv[i] = ok[i] ? ei[e] : 0;
        int c = ok[i] ? (ei[EE + e] >> 2) : 0;
        p[i] = ok[i] ? atomicAdd(&g_cursor[c], 1u) : 0u;
    }
    #pragma unroll
    for (int i = 0; i < 4; i++)
        if (ok[i]) g_binned_src[p[i]] = sv[i];
}

// ---------------------------------------------------------------------------
// K_cluster: one warp per cluster; register accumulation, write row once
__global__ __launch_bounds__(256) void k_cluster(const float* __restrict__ x) {
    int warp = (blockIdx.x * 256 + threadIdx.x) >> 5;
    int lane = threadIdx.x & 31;
    if (warp >= CC) return;
    unsigned base = g_start[warp];
    unsigned cnt = g_hist[warp];
    const float4* x4 = (const float4*)x;
    float4 acc = make_float4(0.f, 0.f, 0.f, 0.f);

    unsigned k = 0;
    for (; k + 32 <= cnt; k += 32) {
        int s = g_binned_src[base + k + lane];
        #pragma unroll
        for (int j = 0; j < 32; j++) {
            int sb = __shfl_sync(0xffffffffu, s, j);
            float4 v = __ldg(&x4[(size_t)sb * 32 + lane]);
            acc.x += v.x; acc.y += v.y; acc.z += v.z; acc.w += v.w;
        }
    }
    int rem = (int)(cnt - k);
    if (rem > 0) {
        int s = (lane < rem) ? g_binned_src[base + k + lane] : 0;
        for (int j = 0; j < rem; j++) {
            int sb = __shfl_sync(0xffffffffu, s, j);
            float4 v = __ldg(&x4[(size_t)sb * 32 + lane]);
            acc.x += v.x; acc.y += v.y; acc.z += v.z; acc.w += v.w;
        }
    }
    ((float4*)g_cagg_x)[(size_t)warp * 32 + lane] = acc;
}

// ---------------------------------------------------------------------------
// K_uniq: fused count + lookback scan + sorted emit; self-cleans bitmap
__global__ __launch_bounds__(256) void k_uniq(float* __restrict__ out) {
    __shared__ unsigned s_warp[8];
    __shared__ unsigned sh_base;
    int b = blockIdx.x, tid = threadIdx.x;
    size_t wbase = (size_t)b * WPB + (size_t)tid * 8;

    unsigned long long w[8];
    unsigned cnt = 0;
    #pragma unroll
    for (int j = 0; j < 8; j++) {
        size_t wi = wbase + j;
        w[j] = (wi < BM_WORDS) ? g_bitmap[wi] : 0ull;
        cnt += (unsigned)__popcll(w[j]);
    }
    unsigned total;
    unsigned excl = block_excl_scan256(cnt, s_warp, &total);
    if (tid == 0) sh_base = lookback(g_ubState, b, total);
    __syncthreads();
    unsigned p = sh_base + excl;

    #pragma unroll
    for (int j = 0; j < 8; j++) {
        unsigned long long wv = w[j];
        if (!wv) continue;
        size_t wi = wbase + j;
        g_bitmap[wi] = 0ull;
        while (wv) {
            int bit = __ffsll((long long)wv) - 1;
            wv &= wv - 1;
            unsigned v = (unsigned)wi * 64u + (unsigned)bit;
            unsigned sc = v / (unsigned)CC;
            unsigned dc = v - sc * (unsigned)CC;
            out[IDX_OFF + p]      = (float)sc;
            out[IDX_OFF + EE + p] = (float)dc;
            out[ATTR_OFF + 3 * p + 0] = g_newpos[dc * 3 + 0] - g_newpos[sc * 3 + 0];
            out[ATTR_OFF + 3 * p + 1] = g_newpos[dc * 3 + 1] - g_newpos[sc * 3 + 1];
            out[ATTR_OFF + 3 * p + 2] = g_newpos[dc * 3 + 2] - g_newpos[sc * 3 + 2];
            p++;
        }
    }
}

// ---------------------------------------------------------------------------
// K_tail: zero the unused tail of idx/attr outputs
__global__ __launch_bounds__(256) void k_tail(float* __restrict__ out) {
    unsigned U = g_ubState[NBLK - 1] & VALM;
    int t = blockIdx.x * 256 + threadIdx.x;
    const int S = 64 * 256;
    for (int p = U + t; p < EE; p += S) {
        out[IDX_OFF + p] = 0.f;
        out[IDX_OFF + EE + p] = 0.f;
        out[ATTR_OFF + 3 * p + 0] = 0.f;
        out[ATTR_OFF + 3 * p + 1] = 0.f;
        out[ATTR_OFF + 3 * p + 2] = 0.f;
    }
}

// ---------------------------------------------------------------------------
// K_gemm: x_new = (cagg_x @ W1 + cagg_e @ W2) / PF
__global__ __launch_bounds__(256) void k_gemm(float* __restrict__ out) {
    __shared__ float s_rows[16][128];
    int col = threadIdx.x & 127;
    int ty = threadIdx.x >> 7;
    int r0 = blockIdx.x * 16;
    for (int i = threadIdx.x; i < 16 * 128; i += 256) {
        int rr = i >> 7, cc = i & 127;
        int gr = r0 + rr;
        s_rows[rr][cc] = (gr < CC) ? g_cagg_x[(size_t)gr * 128 + cc] : 0.f;
    }
    __syncthreads();
    float acc[8] = {0.f, 0.f, 0.f, 0.f, 0.f, 0.f, 0.f, 0.f};
    #pragma unroll 8
    for (int k = 0; k < 128; k += 4) {
        float w0 = __ldg(&g_W1[(k + 0) * 128 + col]);
        float w1 = __ldg(&g_W1[(k + 1) * 128 + col]);
        float w2 = __ldg(&g_W1[(k + 2) * 128 + col]);
        float w3 = __ldg(&g_W1[(k + 3) * 128 + col]);
        #pragma unroll
        for (int r = 0; r < 8; r++) {
            float4 cv = *(const float4*)&s_rows[ty * 8 + r][k];
            acc[r] += cv.x * w0 + cv.y * w1 + cv.z * w2 + cv.w * w3;
        }
    }
    float e0 = __ldg(&g_W2[0 * 128 + col]);
    float e1 = __ldg(&g_W2[1 * 128 + col]);
    float e2 = __ldg(&g_W2[2 * 128 + col]);
    #pragma unroll
    for (int r = 0; r < 8; r++) {
        int gr = r0 + ty * 8 + r;
        if (gr < CC) {
            float ce0 = g_cagg_e[gr * 4 + 0];
            float ce1 = g_cagg_e[gr * 4 + 1];
            float ce2 = g_cagg_e[gr * 4 + 2];
            float res = (acc[r] + ce0 * e0 + ce1 * e1 + ce2 * e2) * 0.25f;
            out[XNEW_OFF + (size_t)gr * 128 + col] = res;
        }
    }
}

// ---------------------------------------------------------------------------
extern "C" void kernel_launch(void* const* d_in, const int* in_sizes, int n_in,
                              void* d_out, int out_size) {
    const float* x   = (const float*)d_in[0];
    const float* pos = (const float*)d_in[1];
    const int*   ei  = (const int*)d_in[2];
    const float* ea  = (const float*)d_in[3];
    const int*   bat = (const int*)d_in[4];
    const float* Wc  = (const float*)d_in[5];
    const float* We  = (const float*)d_in[6];
    const float* Wg  = (const float*)d_in[8];
    float* out = (float*)d_out;

    static cudaStream_t s1 = nullptr;
    static cudaEvent_t eF = nullptr, eJ = nullptr;
    if (s1 == nullptr) {
        cudaStreamCreate(&s1);
        cudaEventCreateWithFlags(&eF, cudaEventDisableTiming);
        cudaEventCreateWithFlags(&eJ, cudaEventDisableTiming);
    }

    // main stream (capture origin)
    k_init<<<269, 256>>>(pos, bat, Wc, We, Wg, out);
    cudaEventRecord(eF, 0);
    cudaStreamWaitEvent(s1, eF, 0);

    // side stream: bitmap -> unique emit -> tail zero (overlaps cluster path)
    k_bitmap<<<(EE + 1023) / 1024, 256, 0, s1>>>(ei);
    k_uniq<<<NBLK, 256, 0, s1>>>(out);
    k_tail<<<64, 256, 0, s1>>>(out);

    // main stream: hist -> scan -> fill -> cluster -> gemm
    k_hist<<<(EE + 1023) / 1024, 256>>>(ei, ea);
    k_scanH<<<SHB, 256>>>();
    k_fill<<<(EE + 1023) / 1024, 256>>>(ei);
    k_cluster<<<(CC * 32 + 255) / 256, 256>>>(x);
    k_gemm<<<(CC + 15) / 16, 256>>>(out);

    cudaEventRecord(eJ, s1);
    cudaStreamWaitEvent(0, eJ, 0);
}